// round 7
// baseline (speedup 1.0000x reference)
#include <cuda_runtime.h>
#include <cuda_fp16.h>
#include <cuda_bf16.h>

// ============================================================================
// GCN 2-layer on GB300, round 6: agg restructured (8 lanes/edge, no shuffles),
// dinv folded into gemm epilogue / agg, k_dinv deleted.
//   prep: deg -> scan -> fill csr (src only)
//   A1 = fp16((x @ W1) * dout_inv)            [HMMA -> g_A half]
//   h  = relu(sum A1[src] * din_inv + b1)     -> g_B half
//   A2 = fp16((h @ W2) * dout_inv)            [HMMA -> g_A half]
//   out = sum A2[src] * din_inv + b2          -> d_out fp32
// ============================================================================

#define NN   100000
#define EMAX 1600000
#define SCAN_CHUNK 2048
#define NBLK ((NN + SCAN_CHUNK - 1) / SCAN_CHUNK)   // 49

__device__ int   g_deg_out[NN];
__device__ int   g_deg_in[NN];
__device__ int   g_csr_ptr[NN + 1];
__device__ int   g_cursor[NN];
__device__ int   g_csr_src[EMAX];
__device__ int   g_bsum[NBLK];
__device__ int   g_boff[NBLK];
__device__ __align__(16) __half g_A[NN * 64];     // gemm outputs (dout-scaled)
__device__ __align__(16) __half g_B[NN * 64];     // layer-1 hidden (relu out)
__device__ __align__(16) __half g_W1t[64 * 128];  // W1^T [n][k] half
__device__ __align__(16) __half g_W2t[64 * 64];   // W2^T [n][k] half

// ---- zero degree counters ----
__global__ void k_zero(int n) {
    int t = blockIdx.x * blockDim.x + threadIdx.x;
    if (t < n) { g_deg_out[t] = 0; g_deg_in[t] = 0; }
}

// ---- degree histogram ----
__global__ void k_deg(const int* __restrict__ src, const int* __restrict__ dst, int E) {
    int e = blockIdx.x * blockDim.x + threadIdx.x;
    if (e < E) {
        atomicAdd(&g_deg_out[src[e]], 1);
        atomicAdd(&g_deg_in[dst[e]], 1);
    }
}

// ---- weight prep: transpose + fp16 convert. W[k][n] -> Wt[n][k] ----
__global__ void k_prepW(const float* __restrict__ W1, const float* __restrict__ W2) {
    int t = blockIdx.x * blockDim.x + threadIdx.x;
    if (t < 64 * 128) {
        int nn_ = t >> 7, k = t & 127;
        g_W1t[t] = __float2half(W1[k * 64 + nn_]);
    } else if (t < 64 * 128 + 64 * 64) {
        int u = t - 64 * 128;
        int nn_ = u >> 6, k = u & 63;
        g_W2t[u] = __float2half(W2[k * 64 + nn_]);
    }
}

// ---- scan phase 1: block-local exclusive scan (2 elems/thread) + block sums ----
__global__ void k_scan1() {
    __shared__ int s[1024];
    int t = threadIdx.x;
    int base = blockIdx.x * SCAN_CHUNK;
    int i0 = base + t * 2;
    int i1 = i0 + 1;
    int v0 = (i0 < NN) ? g_deg_in[i0] : 0;
    int v1 = (i1 < NN) ? g_deg_in[i1] : 0;
    s[t] = v0 + v1;
    __syncthreads();
#pragma unroll
    for (int off = 1; off < 1024; off <<= 1) {
        int v = (t >= off) ? s[t - off] : 0;
        __syncthreads();
        s[t] += v;
        __syncthreads();
    }
    int excl = (t == 0) ? 0 : s[t - 1];
    if (i0 < NN) g_csr_ptr[i0] = excl;
    if (i1 < NN) g_csr_ptr[i1] = excl + v0;
    if (t == 1023) g_bsum[blockIdx.x] = s[1023];
}

// ---- scan phase 2: exclusive scan of block sums ----
__global__ void k_scan2() {
    __shared__ int s[64];
    int t = threadIdx.x;
    int v = (t < NBLK) ? g_bsum[t] : 0;
    s[t] = v;
    __syncthreads();
#pragma unroll
    for (int off = 1; off < 64; off <<= 1) {
        int u = (t >= off) ? s[t - off] : 0;
        __syncthreads();
        s[t] += u;
        __syncthreads();
    }
    if (t < NBLK) g_boff[t] = (t == 0) ? 0 : s[t - 1];
}

// ---- scan phase 3: add block offsets, mirror to cursor, set sentinel ----
__global__ void k_scan3(int E) {
    int i = blockIdx.x * blockDim.x + threadIdx.x;
    if (i < NN) {
        int v = g_csr_ptr[i] + g_boff[i / SCAN_CHUNK];
        g_csr_ptr[i] = v;
        g_cursor[i]  = v;
    }
    if (i == 0) g_csr_ptr[NN] = E;
}

// ---- CSR fill: bucket src by dst ----
__global__ void k_fill(const int* __restrict__ src, const int* __restrict__ dst, int E) {
    int e = blockIdx.x * blockDim.x + threadIdx.x;
    if (e < E) {
        int pos = atomicAdd(&g_cursor[dst[e]], 1);
        g_csr_src[pos] = src[e];
    }
}

// ============================================================================
// HMMA GEMM: g_A[r][c] = fp16( (X[r,:] @ W[:,c]) * rsqrt(max(deg_out[r],1)) )
// Block: 128 rows x 64 cols, 256 threads = 8 warps. K chunked by 16.
// ============================================================================
template<int K, bool HALF_IN>
__global__ void k_gemm_tc(const float* __restrict__ Xf, int n) {
    __shared__ __align__(16) __half sX[128 * 16];  // [r][k], stride 16
    __shared__ __align__(16) __half sW[64 * 16];   // [n][k], stride 16

    const __half* __restrict__ Wt = (K == 128) ? g_W1t : g_W2t;

    int tid = threadIdx.x;
    int lane = tid & 31;
    int warp = tid >> 5;
    int warp_m = warp & 3;
    int warp_n = warp >> 2;
    int g = lane >> 2;
    int tig = lane & 3;
    int row0 = blockIdx.x * 128;

    float acc[2][4][4];
#pragma unroll
    for (int mt = 0; mt < 2; mt++)
#pragma unroll
        for (int nt = 0; nt < 4; nt++)
#pragma unroll
            for (int c = 0; c < 4; c++) acc[mt][nt][c] = 0.f;

    for (int kc = 0; kc < K; kc += 16) {
        if (HALF_IN) {
            int r = tid >> 1, part = tid & 1;
            int gr = row0 + r;
            if (gr < n) {
                *reinterpret_cast<uint4*>(&sX[r * 16 + part * 8]) =
                    *reinterpret_cast<const uint4*>(g_B + (size_t)gr * 64 + kc + part * 8);
            }
        } else {
#pragma unroll
            for (int p = 0; p < 2; p++) {
                int l = tid + p * 256;
                int r = l >> 2, c4 = l & 3;
                int gr = row0 + r;
                if (gr < n) {
                    float4 v = *reinterpret_cast<const float4*>(Xf + (size_t)gr * K + kc + c4 * 4);
                    *reinterpret_cast<__half2*>(&sX[r * 16 + c4 * 4])     = __floats2half2_rn(v.x, v.y);
                    *reinterpret_cast<__half2*>(&sX[r * 16 + c4 * 4 + 2]) = __floats2half2_rn(v.z, v.w);
                }
            }
        }
        if (tid < 128) {
            int nn_ = tid >> 1, part = tid & 1;
            *reinterpret_cast<uint4*>(&sW[nn_ * 16 + part * 8]) =
                *reinterpret_cast<const uint4*>(Wt + (size_t)nn_ * K + kc + part * 8);
        }
        __syncthreads();

#pragma unroll
        for (int mt = 0; mt < 2; mt++) {
            int ar = warp_m * 32 + mt * 16;
            unsigned a0 = *reinterpret_cast<unsigned*>(&sX[(ar + g) * 16 + tig * 2]);
            unsigned a1 = *reinterpret_cast<unsigned*>(&sX[(ar + g + 8) * 16 + tig * 2]);
            unsigned a2 = *reinterpret_cast<unsigned*>(&sX[(ar + g) * 16 + tig * 2 + 8]);
            unsigned a3 = *reinterpret_cast<unsigned*>(&sX[(ar + g + 8) * 16 + tig * 2 + 8]);
#pragma unroll
            for (int nt = 0; nt < 4; nt++) {
                int col = warp_n * 32 + nt * 8 + g;
                unsigned b0 = *reinterpret_cast<unsigned*>(&sW[col * 16 + tig * 2]);
                unsigned b1 = *reinterpret_cast<unsigned*>(&sW[col * 16 + tig * 2 + 8]);
                float* c = acc[mt][nt];
                asm volatile(
                    "mma.sync.aligned.m16n8k16.row.col.f32.f16.f16.f32 "
                    "{%0,%1,%2,%3},{%4,%5,%6,%7},{%8,%9},{%0,%1,%2,%3};"
                    : "+f"(c[0]), "+f"(c[1]), "+f"(c[2]), "+f"(c[3])
                    : "r"(a0), "r"(a1), "r"(a2), "r"(a3), "r"(b0), "r"(b1));
            }
        }
        __syncthreads();
    }

#pragma unroll
    for (int mt = 0; mt < 2; mt++) {
        int row = row0 + warp_m * 32 + mt * 16 + g;
        float s0 = (row     < n) ? rsqrtf((float)max(g_deg_out[row], 1))     : 0.f;
        float s1 = (row + 8 < n) ? rsqrtf((float)max(g_deg_out[row + 8], 1)) : 0.f;
#pragma unroll
        for (int nt = 0; nt < 4; nt++) {
            int col = warp_n * 32 + nt * 8 + tig * 2;
            float* c = acc[mt][nt];
            if (row < n)
                *reinterpret_cast<__half2*>(g_A + (size_t)row * 64 + col) =
                    __floats2half2_rn(c[0] * s0, c[1] * s0);
            if (row + 8 < n)
                *reinterpret_cast<__half2*>(g_A + (size_t)(row + 8) * 64 + col) =
                    __floats2half2_rn(c[2] * s1, c[3] * s1);
        }
    }
}

// ============================================================================
// CSR aggregate, warp per node. 8 lanes per edge (lane loads uint4 = 8 halfs),
// 8 edges in flight per iteration. No shuffles in the edge loop; csr index is
// an 8-lane broadcast load. Final reduce: 16 shfl_xor per node.
// ============================================================================
template<int LAYER>
__global__ void k_agg(const float* __restrict__ bias, float* __restrict__ outp, int n) {
    int gw = (blockIdx.x * blockDim.x + threadIdx.x) >> 5;
    int lane = threadIdx.x & 31;
    if (gw >= n) return;

    int s0 = g_csr_ptr[gw];
    int s1 = g_csr_ptr[gw + 1];
    int sub = lane & 7;     // feature octet: features sub*8 .. sub*8+7
    int grp = lane >> 3;    // edge slot within iteration

    float acc[8];
#pragma unroll
    for (int j = 0; j < 8; j++) acc[j] = 0.f;

    for (int base = s0; base < s1; base += 8) {
        int e0 = base + grp;
        int e1 = base + 4 + grp;
        uint4 h0 = make_uint4(0u, 0u, 0u, 0u);
        uint4 h1 = make_uint4(0u, 0u, 0u, 0u);
        if (e0 < s1) {
            int s = g_csr_src[e0];
            h0 = *reinterpret_cast<const uint4*>(g_A + (size_t)s * 64 + sub * 8);
        }
        if (e1 < s1) {
            int s = g_csr_src[e1];
            h1 = *reinterpret_cast<const uint4*>(g_A + (size_t)s * 64 + sub * 8);
        }
        const __half2* p0 = reinterpret_cast<const __half2*>(&h0);
        const __half2* p1 = reinterpret_cast<const __half2*>(&h1);
#pragma unroll
        for (int q = 0; q < 4; q++) {
            float2 f0 = __half22float2(p0[q]);
            float2 f1 = __half22float2(p1[q]);
            acc[q * 2]     += f0.x + f1.x;
            acc[q * 2 + 1] += f0.y + f1.y;
        }
    }

    // reduce across the 4 edge-slot groups (all lanes end with full sums)
#pragma unroll
    for (int j = 0; j < 8; j++) {
        acc[j] += __shfl_xor_sync(0xffffffffu, acc[j], 8);
        acc[j] += __shfl_xor_sync(0xffffffffu, acc[j], 16);
    }

    float sc = rsqrtf((float)max(s1 - s0, 1));   // din_inv
    int f = sub * 8 + grp * 2;                   // each lane writes 2 features
    float ox = fmaf(acc[grp * 2],     sc, bias[f]);
    float oy = fmaf(acc[grp * 2 + 1], sc, bias[f + 1]);
    if (LAYER == 1) {
        ox = fmaxf(ox, 0.f);
        oy = fmaxf(oy, 0.f);
        *reinterpret_cast<__half2*>(g_B + (size_t)gw * 64 + f) = __floats2half2_rn(ox, oy);
    } else {
        *reinterpret_cast<float2*>(outp + (size_t)gw * 64 + f) = make_float2(ox, oy);
    }
}

extern "C" void kernel_launch(void* const* d_in, const int* in_sizes, int n_in,
                              void* d_out, int out_size) {
    const float* x   = (const float*)d_in[0];
    const int*   src = (const int*)d_in[1];
    const int*   dst = (const int*)d_in[2];
    const float* W1  = (const float*)d_in[3];
    const float* b1  = (const float*)d_in[4];
    const float* W2  = (const float*)d_in[5];
    const float* b2  = (const float*)d_in[6];
    float* out = (float*)d_out;

    const int n = NN;
    const int E = in_sizes[1];

    const int T = 256;
    int grid_edges = (E + T - 1) / T;
    int grid_nodes = (n + T - 1) / T;
    int grid_gemm  = (n + 127) / 128;
    int grid_agg   = (n * 32 + T - 1) / T;
    int grid_prepw = (64 * 128 + 64 * 64 + T - 1) / T;

    k_prepW<<<grid_prepw, T>>>(W1, W2);
    k_zero<<<grid_nodes, T>>>(n);
    k_deg<<<grid_edges, T>>>(src, dst, E);
    k_scan1<<<NBLK, 1024>>>();
    k_scan2<<<1, 64>>>();
    k_scan3<<<grid_nodes, T>>>(E);
    k_fill<<<grid_edges, T>>>(src, dst, E);

    k_gemm_tc<128, false><<<grid_gemm, T>>>(x, n);
    k_agg<1><<<grid_agg, T>>>(b1, nullptr, n);

    k_gemm_tc<64, true><<<grid_gemm, T>>>(nullptr, n);
    k_agg<2><<<grid_agg, T>>>(b2, out, n);
}

// round 8
// speedup vs baseline: 1.4075x; 1.4075x over previous
#include <cuda_runtime.h>
#include <cuda_fp16.h>
#include <cuda_bf16.h>

// ============================================================================
// GCN 2-layer on GB300, round 7: fix R6's register-array spill in k_agg
// (dynamic index -> local memory). Lanes 0-7 now write full octets with
// compile-time indices. k_zero fused into k_prep.
//   prep: {zero degs + W->half^T} -> deg -> scan -> fill csr (src only)
//   A1 = fp16((x @ W1) * dout_inv)            [HMMA -> g_A half]
//   h  = relu(sum A1[src] * din_inv + b1)     -> g_B half
//   A2 = fp16((h @ W2) * dout_inv)            [HMMA -> g_A half]
//   out = sum A2[src] * din_inv + b2          -> d_out fp32
// ============================================================================

#define NN   100000
#define EMAX 1600000
#define SCAN_CHUNK 2048
#define NBLK ((NN + SCAN_CHUNK - 1) / SCAN_CHUNK)   // 49

__device__ int   g_deg_out[NN];
__device__ int   g_deg_in[NN];
__device__ int   g_csr_ptr[NN + 1];
__device__ int   g_cursor[NN];
__device__ int   g_csr_src[EMAX];
__device__ int   g_bsum[NBLK];
__device__ int   g_boff[NBLK];
__device__ __align__(16) __half g_A[NN * 64];     // gemm outputs (dout-scaled)
__device__ __align__(16) __half g_B[NN * 64];     // layer-1 hidden (relu out)
__device__ __align__(16) __half g_W1t[64 * 128];  // W1^T [n][k] half
__device__ __align__(16) __half g_W2t[64 * 64];   // W2^T [n][k] half

// ---- fused prep: zero degree counters + transpose/convert weights ----
__global__ void k_prep(const float* __restrict__ W1, const float* __restrict__ W2, int n) {
    int t = blockIdx.x * blockDim.x + threadIdx.x;
    if (t < n) { g_deg_out[t] = 0; g_deg_in[t] = 0; }
    if (t < 64 * 128) {
        int nn_ = t >> 7, k = t & 127;
        g_W1t[t] = __float2half(W1[k * 64 + nn_]);
    } else if (t < 64 * 128 + 64 * 64) {
        int u = t - 64 * 128;
        int nn_ = u >> 6, k = u & 63;
        g_W2t[u] = __float2half(W2[k * 64 + nn_]);
    }
}

// ---- degree histogram ----
__global__ void k_deg(const int* __restrict__ src, const int* __restrict__ dst, int E) {
    int e = blockIdx.x * blockDim.x + threadIdx.x;
    if (e < E) {
        atomicAdd(&g_deg_out[src[e]], 1);
        atomicAdd(&g_deg_in[dst[e]], 1);
    }
}

// ---- scan phase 1 ----
__global__ void k_scan1() {
    __shared__ int s[1024];
    int t = threadIdx.x;
    int base = blockIdx.x * SCAN_CHUNK;
    int i0 = base + t * 2;
    int i1 = i0 + 1;
    int v0 = (i0 < NN) ? g_deg_in[i0] : 0;
    int v1 = (i1 < NN) ? g_deg_in[i1] : 0;
    s[t] = v0 + v1;
    __syncthreads();
#pragma unroll
    for (int off = 1; off < 1024; off <<= 1) {
        int v = (t >= off) ? s[t - off] : 0;
        __syncthreads();
        s[t] += v;
        __syncthreads();
    }
    int excl = (t == 0) ? 0 : s[t - 1];
    if (i0 < NN) g_csr_ptr[i0] = excl;
    if (i1 < NN) g_csr_ptr[i1] = excl + v0;
    if (t == 1023) g_bsum[blockIdx.x] = s[1023];
}

// ---- scan phase 2 ----
__global__ void k_scan2() {
    __shared__ int s[64];
    int t = threadIdx.x;
    int v = (t < NBLK) ? g_bsum[t] : 0;
    s[t] = v;
    __syncthreads();
#pragma unroll
    for (int off = 1; off < 64; off <<= 1) {
        int u = (t >= off) ? s[t - off] : 0;
        __syncthreads();
        s[t] += u;
        __syncthreads();
    }
    if (t < NBLK) g_boff[t] = (t == 0) ? 0 : s[t - 1];
}

// ---- scan phase 3 ----
__global__ void k_scan3(int E) {
    int i = blockIdx.x * blockDim.x + threadIdx.x;
    if (i < NN) {
        int v = g_csr_ptr[i] + g_boff[i / SCAN_CHUNK];
        g_csr_ptr[i] = v;
        g_cursor[i]  = v;
    }
    if (i == 0) g_csr_ptr[NN] = E;
}

// ---- CSR fill ----
__global__ void k_fill(const int* __restrict__ src, const int* __restrict__ dst, int E) {
    int e = blockIdx.x * blockDim.x + threadIdx.x;
    if (e < E) {
        int pos = atomicAdd(&g_cursor[dst[e]], 1);
        g_csr_src[pos] = src[e];
    }
}

// ============================================================================
// HMMA GEMM: g_A[r][c] = fp16( (X[r,:] @ W[:,c]) * rsqrt(max(deg_out[r],1)) )
// ============================================================================
template<int K, bool HALF_IN>
__global__ void k_gemm_tc(const float* __restrict__ Xf, int n) {
    __shared__ __align__(16) __half sX[128 * 16];
    __shared__ __align__(16) __half sW[64 * 16];

    const __half* __restrict__ Wt = (K == 128) ? g_W1t : g_W2t;

    int tid = threadIdx.x;
    int lane = tid & 31;
    int warp = tid >> 5;
    int warp_m = warp & 3;
    int warp_n = warp >> 2;
    int g = lane >> 2;
    int tig = lane & 3;
    int row0 = blockIdx.x * 128;

    float acc[2][4][4];
#pragma unroll
    for (int mt = 0; mt < 2; mt++)
#pragma unroll
        for (int nt = 0; nt < 4; nt++)
#pragma unroll
            for (int c = 0; c < 4; c++) acc[mt][nt][c] = 0.f;

    for (int kc = 0; kc < K; kc += 16) {
        if (HALF_IN) {
            int r = tid >> 1, part = tid & 1;
            int gr = row0 + r;
            if (gr < n) {
                *reinterpret_cast<uint4*>(&sX[r * 16 + part * 8]) =
                    *reinterpret_cast<const uint4*>(g_B + (size_t)gr * 64 + kc + part * 8);
            }
        } else {
#pragma unroll
            for (int p = 0; p < 2; p++) {
                int l = tid + p * 256;
                int r = l >> 2, c4 = l & 3;
                int gr = row0 + r;
                if (gr < n) {
                    float4 v = *reinterpret_cast<const float4*>(Xf + (size_t)gr * K + kc + c4 * 4);
                    *reinterpret_cast<__half2*>(&sX[r * 16 + c4 * 4])     = __floats2half2_rn(v.x, v.y);
                    *reinterpret_cast<__half2*>(&sX[r * 16 + c4 * 4 + 2]) = __floats2half2_rn(v.z, v.w);
                }
            }
        }
        if (tid < 128) {
            int nn_ = tid >> 1, part = tid & 1;
            *reinterpret_cast<uint4*>(&sW[nn_ * 16 + part * 8]) =
                *reinterpret_cast<const uint4*>(Wt + (size_t)nn_ * K + kc + part * 8);
        }
        __syncthreads();

#pragma unroll
        for (int mt = 0; mt < 2; mt++) {
            int ar = warp_m * 32 + mt * 16;
            unsigned a0 = *reinterpret_cast<unsigned*>(&sX[(ar + g) * 16 + tig * 2]);
            unsigned a1 = *reinterpret_cast<unsigned*>(&sX[(ar + g + 8) * 16 + tig * 2]);
            unsigned a2 = *reinterpret_cast<unsigned*>(&sX[(ar + g) * 16 + tig * 2 + 8]);
            unsigned a3 = *reinterpret_cast<unsigned*>(&sX[(ar + g + 8) * 16 + tig * 2 + 8]);
#pragma unroll
            for (int nt = 0; nt < 4; nt++) {
                int col = warp_n * 32 + nt * 8 + g;
                unsigned b0 = *reinterpret_cast<unsigned*>(&sW[col * 16 + tig * 2]);
                unsigned b1 = *reinterpret_cast<unsigned*>(&sW[col * 16 + tig * 2 + 8]);
                float* c = acc[mt][nt];
                asm volatile(
                    "mma.sync.aligned.m16n8k16.row.col.f32.f16.f16.f32 "
                    "{%0,%1,%2,%3},{%4,%5,%6,%7},{%8,%9},{%0,%1,%2,%3};"
                    : "+f"(c[0]), "+f"(c[1]), "+f"(c[2]), "+f"(c[3])
                    : "r"(a0), "r"(a1), "r"(a2), "r"(a3), "r"(b0), "r"(b1));
            }
        }
        __syncthreads();
    }

#pragma unroll
    for (int mt = 0; mt < 2; mt++) {
        int row = row0 + warp_m * 32 + mt * 16 + g;
        float s0 = (row     < n) ? rsqrtf((float)max(g_deg_out[row], 1))     : 0.f;
        float s1 = (row + 8 < n) ? rsqrtf((float)max(g_deg_out[row + 8], 1)) : 0.f;
#pragma unroll
        for (int nt = 0; nt < 4; nt++) {
            int col = warp_n * 32 + nt * 8 + tig * 2;
            float* c = acc[mt][nt];
            if (row < n)
                *reinterpret_cast<__half2*>(g_A + (size_t)row * 64 + col) =
                    __floats2half2_rn(c[0] * s0, c[1] * s0);
            if (row + 8 < n)
                *reinterpret_cast<__half2*>(g_A + (size_t)(row + 8) * 64 + col) =
                    __floats2half2_rn(c[2] * s1, c[3] * s1);
        }
    }
}

// ============================================================================
// CSR aggregate, warp per node. 8 lanes per edge (lane loads uint4 = 8 halfs),
// 8 edges in flight. After the xor-reduction lanes 0-7 hold the full sums for
// their feature octet and write it with COMPILE-TIME indices (no spill).
// ============================================================================
template<int LAYER>
__global__ void k_agg(const float* __restrict__ bias, float* __restrict__ outp, int n) {
    int gw = (blockIdx.x * blockDim.x + threadIdx.x) >> 5;
    int lane = threadIdx.x & 31;
    if (gw >= n) return;

    int s0 = g_csr_ptr[gw];
    int s1 = g_csr_ptr[gw + 1];
    int sub = lane & 7;     // feature octet: features sub*8 .. sub*8+7
    int grp = lane >> 3;    // edge slot within iteration

    float acc[8];
#pragma unroll
    for (int j = 0; j < 8; j++) acc[j] = 0.f;

    for (int base = s0; base < s1; base += 8) {
        int e0 = base + grp;
        int e1 = base + 4 + grp;
        uint4 h0 = make_uint4(0u, 0u, 0u, 0u);
        uint4 h1 = make_uint4(0u, 0u, 0u, 0u);
        if (e0 < s1) {
            int s = g_csr_src[e0];
            h0 = *reinterpret_cast<const uint4*>(g_A + (size_t)s * 64 + sub * 8);
        }
        if (e1 < s1) {
            int s = g_csr_src[e1];
            h1 = *reinterpret_cast<const uint4*>(g_A + (size_t)s * 64 + sub * 8);
        }
        const __half2* p0 = reinterpret_cast<const __half2*>(&h0);
        const __half2* p1 = reinterpret_cast<const __half2*>(&h1);
#pragma unroll
        for (int q = 0; q < 4; q++) {
            float2 f0 = __half22float2(p0[q]);
            float2 f1 = __half22float2(p1[q]);
            acc[q * 2]     += f0.x + f1.x;
            acc[q * 2 + 1] += f0.y + f1.y;
        }
    }

    // reduce across the 4 edge-slot groups
#pragma unroll
    for (int j = 0; j < 8; j++) {
        acc[j] += __shfl_xor_sync(0xffffffffu, acc[j], 8);
        acc[j] += __shfl_xor_sync(0xffffffffu, acc[j], 16);
    }

    // lanes 0-7 write their whole octet (constant indices, coalesced 128B)
    if (grp == 0) {
        float sc = rsqrtf((float)max(s1 - s0, 1));   // din_inv
        const float* bp = bias + sub * 8;
        float o[8];
#pragma unroll
        for (int j = 0; j < 8; j++) {
            o[j] = fmaf(acc[j], sc, bp[j]);
            if (LAYER == 1) o[j] = fmaxf(o[j], 0.f);
        }
        if (LAYER == 1) {
            uint4 pack;
            __half2* hp = reinterpret_cast<__half2*>(&pack);
            hp[0] = __floats2half2_rn(o[0], o[1]);
            hp[1] = __floats2half2_rn(o[2], o[3]);
            hp[2] = __floats2half2_rn(o[4], o[5]);
            hp[3] = __floats2half2_rn(o[6], o[7]);
            *reinterpret_cast<uint4*>(g_B + (size_t)gw * 64 + sub * 8) = pack;
        } else {
            float* op = outp + (size_t)gw * 64 + sub * 8;
            *reinterpret_cast<float4*>(op)     = make_float4(o[0], o[1], o[2], o[3]);
            *reinterpret_cast<float4*>(op + 4) = make_float4(o[4], o[5], o[6], o[7]);
        }
    }
}

extern "C" void kernel_launch(void* const* d_in, const int* in_sizes, int n_in,
                              void* d_out, int out_size) {
    const float* x   = (const float*)d_in[0];
    const int*   src = (const int*)d_in[1];
    const int*   dst = (const int*)d_in[2];
    const float* W1  = (const float*)d_in[3];
    const float* b1  = (const float*)d_in[4];
    const float* W2  = (const float*)d_in[5];
    const float* b2  = (const float*)d_in[6];
    float* out = (float*)d_out;

    const int n = NN;
    const int E = in_sizes[1];

    const int T = 256;
    int grid_edges = (E + T - 1) / T;
    int grid_nodes = (n + T - 1) / T;
    int grid_gemm  = (n + 127) / 128;
    int grid_agg   = (n * 32 + T - 1) / T;

    k_prep<<<grid_nodes, T>>>(W1, W2, n);
    k_deg<<<grid_edges, T>>>(src, dst, E);
    k_scan1<<<NBLK, 1024>>>();
    k_scan2<<<1, 64>>>();
    k_scan3<<<grid_nodes, T>>>(E);
    k_fill<<<grid_edges, T>>>(src, dst, E);

    k_gemm_tc<128, false><<<grid_gemm, T>>>(x, n);
    k_agg<1><<<grid_agg, T>>>(b1, nullptr, n);

    k_gemm_tc<64, true><<<grid_gemm, T>>>(nullptr, n);
    k_agg<2><<<grid_agg, T>>>(b2, out, n);
}

// round 9
// speedup vs baseline: 1.5326x; 1.0889x over previous
#include <cuda_runtime.h>
#include <cuda_fp16.h>
#include <cuda_bf16.h>

// ============================================================================
// GCN 2-layer on GB300, round 8:
//  - prefix scan replaced by atomic segment assignment (CSR segment order is
//    irrelevant; only contiguity matters)
//  - CSR build (deg_in -> assign -> fill) overlapped with GEMM1 via stream
//    fork-join inside graph capture
//   A1 = fp16((x @ W1) * dout_inv)            [HMMA -> g_A half]
//   h  = relu(sum A1[src] * din_inv + b1)     -> g_B half
//   A2 = fp16((h @ W2) * dout_inv)            [HMMA -> g_A half]
//   out = sum A2[src] * din_inv + b2          -> d_out fp32
// ============================================================================

#define NN   100000
#define EMAX 1600000

__device__ int   g_deg_out[NN];
__device__ int   g_deg_in[NN];
__device__ int   g_csr_ptr[NN];
__device__ int   g_cursor[NN];
__device__ int   g_csr_src[EMAX];
__device__ int   g_total;
__device__ __align__(16) __half g_A[NN * 64];     // gemm outputs (dout-scaled)
__device__ __align__(16) __half g_B[NN * 64];     // layer-1 hidden (relu out)
__device__ __align__(16) __half g_W1t[64 * 128];  // W1^T [n][k] half
__device__ __align__(16) __half g_W2t[64 * 64];   // W2^T [n][k] half

// ---- fused prep: zero degree counters + total + transpose/convert weights ----
__global__ void k_prep(const float* __restrict__ W1, const float* __restrict__ W2, int n) {
    int t = blockIdx.x * blockDim.x + threadIdx.x;
    if (t < n) { g_deg_out[t] = 0; g_deg_in[t] = 0; }
    if (t == 0) g_total = 0;
    if (t < 64 * 128) {
        int nn_ = t >> 7, k = t & 127;
        g_W1t[t] = __float2half(W1[k * 64 + nn_]);
    } else if (t < 64 * 128 + 64 * 64) {
        int u = t - 64 * 128;
        int nn_ = u >> 6, k = u & 63;
        g_W2t[u] = __float2half(W2[k * 64 + nn_]);
    }
}

// ---- out-degree histogram (default stream; feeds gemm1 epilogue) ----
__global__ void k_deg_out(const int* __restrict__ src, int E) {
    int e = blockIdx.x * blockDim.x + threadIdx.x;
    if (e < E) atomicAdd(&g_deg_out[src[e]], 1);
}

// ---- in-degree histogram (side stream; feeds CSR build) ----
__global__ void k_deg_in(const int* __restrict__ dst, int E) {
    int e = blockIdx.x * blockDim.x + threadIdx.x;
    if (e < E) atomicAdd(&g_deg_in[dst[e]], 1);
}

// ---- segment assignment: contiguous (order-free) CSR segments via atomic ----
__global__ void k_assign(int n) {
    int i = blockIdx.x * blockDim.x + threadIdx.x;
    if (i < n) {
        int d = g_deg_in[i];
        int p = atomicAdd(&g_total, d);
        g_csr_ptr[i] = p;
        g_cursor[i]  = p;
    }
}

// ---- CSR fill ----
__global__ void k_fill(const int* __restrict__ src, const int* __restrict__ dst, int E) {
    int e = blockIdx.x * blockDim.x + threadIdx.x;
    if (e < E) {
        int pos = atomicAdd(&g_cursor[dst[e]], 1);
        g_csr_src[pos] = src[e];
    }
}

// ============================================================================
// HMMA GEMM: g_A[r][c] = fp16( (X[r,:] @ W[:,c]) * rsqrt(max(deg_out[r],1)) )
// ============================================================================
template<int K, bool HALF_IN>
__global__ void k_gemm_tc(const float* __restrict__ Xf, int n) {
    __shared__ __align__(16) __half sX[128 * 16];
    __shared__ __align__(16) __half sW[64 * 16];

    const __half* __restrict__ Wt = (K == 128) ? g_W1t : g_W2t;

    int tid = threadIdx.x;
    int lane = tid & 31;
    int warp = tid >> 5;
    int warp_m = warp & 3;
    int warp_n = warp >> 2;
    int g = lane >> 2;
    int tig = lane & 3;
    int row0 = blockIdx.x * 128;

    float acc[2][4][4];
#pragma unroll
    for (int mt = 0; mt < 2; mt++)
#pragma unroll
        for (int nt = 0; nt < 4; nt++)
#pragma unroll
            for (int c = 0; c < 4; c++) acc[mt][nt][c] = 0.f;

    for (int kc = 0; kc < K; kc += 16) {
        if (HALF_IN) {
            int r = tid >> 1, part = tid & 1;
            int gr = row0 + r;
            if (gr < n) {
                *reinterpret_cast<uint4*>(&sX[r * 16 + part * 8]) =
                    *reinterpret_cast<const uint4*>(g_B + (size_t)gr * 64 + kc + part * 8);
            }
        } else {
#pragma unroll
            for (int p = 0; p < 2; p++) {
                int l = tid + p * 256;
                int r = l >> 2, c4 = l & 3;
                int gr = row0 + r;
                if (gr < n) {
                    float4 v = *reinterpret_cast<const float4*>(Xf + (size_t)gr * K + kc + c4 * 4);
                    *reinterpret_cast<__half2*>(&sX[r * 16 + c4 * 4])     = __floats2half2_rn(v.x, v.y);
                    *reinterpret_cast<__half2*>(&sX[r * 16 + c4 * 4 + 2]) = __floats2half2_rn(v.z, v.w);
                }
            }
        }
        if (tid < 128) {
            int nn_ = tid >> 1, part = tid & 1;
            *reinterpret_cast<uint4*>(&sW[nn_ * 16 + part * 8]) =
                *reinterpret_cast<const uint4*>(Wt + (size_t)nn_ * K + kc + part * 8);
        }
        __syncthreads();

#pragma unroll
        for (int mt = 0; mt < 2; mt++) {
            int ar = warp_m * 32 + mt * 16;
            unsigned a0 = *reinterpret_cast<unsigned*>(&sX[(ar + g) * 16 + tig * 2]);
            unsigned a1 = *reinterpret_cast<unsigned*>(&sX[(ar + g + 8) * 16 + tig * 2]);
            unsigned a2 = *reinterpret_cast<unsigned*>(&sX[(ar + g) * 16 + tig * 2 + 8]);
            unsigned a3 = *reinterpret_cast<unsigned*>(&sX[(ar + g + 8) * 16 + tig * 2 + 8]);
#pragma unroll
            for (int nt = 0; nt < 4; nt++) {
                int col = warp_n * 32 + nt * 8 + g;
                unsigned b0 = *reinterpret_cast<unsigned*>(&sW[col * 16 + tig * 2]);
                unsigned b1 = *reinterpret_cast<unsigned*>(&sW[col * 16 + tig * 2 + 8]);
                float* c = acc[mt][nt];
                asm volatile(
                    "mma.sync.aligned.m16n8k16.row.col.f32.f16.f16.f32 "
                    "{%0,%1,%2,%3},{%4,%5,%6,%7},{%8,%9},{%0,%1,%2,%3};"
                    : "+f"(c[0]), "+f"(c[1]), "+f"(c[2]), "+f"(c[3])
                    : "r"(a0), "r"(a1), "r"(a2), "r"(a3), "r"(b0), "r"(b1));
            }
        }
        __syncthreads();
    }

#pragma unroll
    for (int mt = 0; mt < 2; mt++) {
        int row = row0 + warp_m * 32 + mt * 16 + g;
        float s0 = (row     < n) ? rsqrtf((float)max(g_deg_out[row], 1))     : 0.f;
        float s1 = (row + 8 < n) ? rsqrtf((float)max(g_deg_out[row + 8], 1)) : 0.f;
#pragma unroll
        for (int nt = 0; nt < 4; nt++) {
            int col = warp_n * 32 + nt * 8 + tig * 2;
            float* c = acc[mt][nt];
            if (row < n)
                *reinterpret_cast<__half2*>(g_A + (size_t)row * 64 + col) =
                    __floats2half2_rn(c[0] * s0, c[1] * s0);
            if (row + 8 < n)
                *reinterpret_cast<__half2*>(g_A + (size_t)(row + 8) * 64 + col) =
                    __floats2half2_rn(c[2] * s1, c[3] * s1);
        }
    }
}

// ============================================================================
// CSR aggregate, warp per node. 8 lanes per edge (lane loads uint4 = 8 halfs),
// 8 edges in flight. Segment = [ptr, ptr + deg_in).
// ============================================================================
template<int LAYER>
__global__ void k_agg(const float* __restrict__ bias, float* __restrict__ outp, int n) {
    int gw = (blockIdx.x * blockDim.x + threadIdx.x) >> 5;
    int lane = threadIdx.x & 31;
    if (gw >= n) return;

    int s0 = g_csr_ptr[gw];
    int deg = g_deg_in[gw];
    int s1 = s0 + deg;
    int sub = lane & 7;     // feature octet: features sub*8 .. sub*8+7
    int grp = lane >> 3;    // edge slot within iteration

    float acc[8];
#pragma unroll
    for (int j = 0; j < 8; j++) acc[j] = 0.f;

    for (int base = s0; base < s1; base += 8) {
        int e0 = base + grp;
        int e1 = base + 4 + grp;
        uint4 h0 = make_uint4(0u, 0u, 0u, 0u);
        uint4 h1 = make_uint4(0u, 0u, 0u, 0u);
        if (e0 < s1) {
            int s = g_csr_src[e0];
            h0 = *reinterpret_cast<const uint4*>(g_A + (size_t)s * 64 + sub * 8);
        }
        if (e1 < s1) {
            int s = g_csr_src[e1];
            h1 = *reinterpret_cast<const uint4*>(g_A + (size_t)s * 64 + sub * 8);
        }
        const __half2* p0 = reinterpret_cast<const __half2*>(&h0);
        const __half2* p1 = reinterpret_cast<const __half2*>(&h1);
#pragma unroll
        for (int q = 0; q < 4; q++) {
            float2 f0 = __half22float2(p0[q]);
            float2 f1 = __half22float2(p1[q]);
            acc[q * 2]     += f0.x + f1.x;
            acc[q * 2 + 1] += f0.y + f1.y;
        }
    }

    // reduce across the 4 edge-slot groups
#pragma unroll
    for (int j = 0; j < 8; j++) {
        acc[j] += __shfl_xor_sync(0xffffffffu, acc[j], 8);
        acc[j] += __shfl_xor_sync(0xffffffffu, acc[j], 16);
    }

    // lanes 0-7 write their whole octet (constant indices, coalesced)
    if (grp == 0) {
        float sc = rsqrtf((float)max(deg, 1));   // din_inv
        const float* bp = bias + sub * 8;
        float o[8];
#pragma unroll
        for (int j = 0; j < 8; j++) {
            o[j] = fmaf(acc[j], sc, bp[j]);
            if (LAYER == 1) o[j] = fmaxf(o[j], 0.f);
        }
        if (LAYER == 1) {
            uint4 pack;
            __half2* hp = reinterpret_cast<__half2*>(&pack);
            hp[0] = __floats2half2_rn(o[0], o[1]);
            hp[1] = __floats2half2_rn(o[2], o[3]);
            hp[2] = __floats2half2_rn(o[4], o[5]);
            hp[3] = __floats2half2_rn(o[6], o[7]);
            *reinterpret_cast<uint4*>(g_B + (size_t)gw * 64 + sub * 8) = pack;
        } else {
            float* op = outp + (size_t)gw * 64 + sub * 8;
            *reinterpret_cast<float4*>(op)     = make_float4(o[0], o[1], o[2], o[3]);
            *reinterpret_cast<float4*>(op + 4) = make_float4(o[4], o[5], o[6], o[7]);
        }
    }
}

extern "C" void kernel_launch(void* const* d_in, const int* in_sizes, int n_in,
                              void* d_out, int out_size) {
    const float* x   = (const float*)d_in[0];
    const int*   src = (const int*)d_in[1];
    const int*   dst = (const int*)d_in[2];
    const float* W1  = (const float*)d_in[3];
    const float* b1  = (const float*)d_in[4];
    const float* W2  = (const float*)d_in[5];
    const float* b2  = (const float*)d_in[6];
    float* out = (float*)d_out;

    const int n = NN;
    const int E = in_sizes[1];

    const int T = 256;
    int grid_edges = (E + T - 1) / T;
    int grid_nodes = (n + T - 1) / T;
    int grid_gemm  = (n + 127) / 128;
    int grid_agg   = (n * 32 + T - 1) / T;

    // fork-join plumbing (host objects only; no device allocation)
    cudaStream_t s1;
    cudaStreamCreateWithFlags(&s1, cudaStreamNonBlocking);
    cudaEvent_t evFork, evJoin;
    cudaEventCreateWithFlags(&evFork, cudaEventDisableTiming);
    cudaEventCreateWithFlags(&evJoin, cudaEventDisableTiming);

    // prep on main stream, then fork
    k_prep<<<grid_nodes, T>>>(W1, W2, n);
    cudaEventRecord(evFork, 0);
    cudaStreamWaitEvent(s1, evFork, 0);

    // branch A (main): out-degrees -> GEMM1
    k_deg_out<<<grid_edges, T>>>(src, E);
    k_gemm_tc<128, false><<<grid_gemm, T>>>(x, n);

    // branch B (s1): in-degrees -> segment assign -> CSR fill
    k_deg_in<<<grid_edges, T, 0, s1>>>(dst, E);
    k_assign<<<grid_nodes, T, 0, s1>>>(n);
    k_fill<<<grid_edges, T, 0, s1>>>(src, dst, E);
    cudaEventRecord(evJoin, s1);
    cudaStreamWaitEvent(0, evJoin, 0);

    // layer 1 aggregate, layer 2
    k_agg<1><<<grid_agg, T>>>(b1, nullptr, n);
    k_gemm_tc<64, true><<<grid_gemm, T>>>(nullptr, n);
    k_agg<2><<<grid_agg, T>>>(b2, out, n);

    cudaEventDestroy(evFork);
    cudaEventDestroy(evJoin);
    cudaStreamDestroy(s1);
}

// round 10
// speedup vs baseline: 1.5591x; 1.0173x over previous
#include <cuda_runtime.h>
#include <cuda_fp16.h>
#include <cuda_bf16.h>

// ============================================================================
// GCN 2-layer on GB300, round 9:
//  - deg_out+deg_in fused into ONE pre-fork kernel, 4 edges/thread (int4)
//  - k_fill vectorized 4 edges/thread
//  - GEMM K-chunk 32 with conflict-free padded smem (stride 40 halfs)
//  - fork: gemm1 (tensor/DRAM) || assign+fill (L2 atomics) - disjoint resources
// ============================================================================

#define NN   100000
#define EMAX 1600000

__device__ int   g_deg_out[NN];
__device__ int   g_deg_in[NN];
__device__ int   g_csr_ptr[NN];
__device__ int   g_cursor[NN];
__device__ int   g_csr_src[EMAX];
__device__ int   g_total;
__device__ __align__(16) __half g_A[NN * 64];     // gemm outputs (dout-scaled)
__device__ __align__(16) __half g_B[NN * 64];     // layer-1 hidden (relu out)
__device__ __align__(16) __half g_W1t[64 * 128];  // W1^T [n][k] half
__device__ __align__(16) __half g_W2t[64 * 64];   // W2^T [n][k] half

// ---- fused prep: zero degree counters + total + transpose/convert weights ----
__global__ void k_prep(const float* __restrict__ W1, const float* __restrict__ W2, int n) {
    int t = blockIdx.x * blockDim.x + threadIdx.x;
    if (t < n) { g_deg_out[t] = 0; g_deg_in[t] = 0; }
    if (t == 0) g_total = 0;
    if (t < 64 * 128) {
        int nn_ = t >> 7, k = t & 127;
        g_W1t[t] = __float2half(W1[k * 64 + nn_]);
    } else if (t < 64 * 128 + 64 * 64) {
        int u = t - 64 * 128;
        int nn_ = u >> 6, k = u & 63;
        g_W2t[u] = __float2half(W2[k * 64 + nn_]);
    }
}

// ---- fused degree histogram: 4 edges/thread, both degrees in one pass ----
__global__ void k_deg(const int* __restrict__ src, const int* __restrict__ dst, int E) {
    int t = blockIdx.x * blockDim.x + threadIdx.x;
    int e = t * 4;
    if (e + 3 < E) {
        int4 s4 = *reinterpret_cast<const int4*>(src + e);
        int4 d4 = *reinterpret_cast<const int4*>(dst + e);
        atomicAdd(&g_deg_out[s4.x], 1);
        atomicAdd(&g_deg_out[s4.y], 1);
        atomicAdd(&g_deg_out[s4.z], 1);
        atomicAdd(&g_deg_out[s4.w], 1);
        atomicAdd(&g_deg_in[d4.x], 1);
        atomicAdd(&g_deg_in[d4.y], 1);
        atomicAdd(&g_deg_in[d4.z], 1);
        atomicAdd(&g_deg_in[d4.w], 1);
    } else {
        for (; e < E; e++) {
            atomicAdd(&g_deg_out[src[e]], 1);
            atomicAdd(&g_deg_in[dst[e]], 1);
        }
    }
}

// ---- segment assignment: contiguous (order-free) CSR segments via atomic ----
__global__ void k_assign(int n) {
    int i = blockIdx.x * blockDim.x + threadIdx.x;
    if (i < n) {
        int d = g_deg_in[i];
        int p = atomicAdd(&g_total, d);
        g_csr_ptr[i] = p;
        g_cursor[i]  = p;
    }
}

// ---- CSR fill: 4 edges/thread ----
__global__ void k_fill(const int* __restrict__ src, const int* __restrict__ dst, int E) {
    int t = blockIdx.x * blockDim.x + threadIdx.x;
    int e = t * 4;
    if (e + 3 < E) {
        int4 s4 = *reinterpret_cast<const int4*>(src + e);
        int4 d4 = *reinterpret_cast<const int4*>(dst + e);
        g_csr_src[atomicAdd(&g_cursor[d4.x], 1)] = s4.x;
        g_csr_src[atomicAdd(&g_cursor[d4.y], 1)] = s4.y;
        g_csr_src[atomicAdd(&g_cursor[d4.z], 1)] = s4.z;
        g_csr_src[atomicAdd(&g_cursor[d4.w], 1)] = s4.w;
    } else {
        for (; e < E; e++)
            g_csr_src[atomicAdd(&g_cursor[dst[e]], 1)] = src[e];
    }
}

// ============================================================================
// HMMA GEMM: g_A[r][c] = fp16( (X[r,:] @ W[:,c]) * rsqrt(max(deg_out[r],1)) )
// Block 128x64, 256 threads, K chunked by 32. Padded smem stride 40 halfs
// (20 words; g*20 mod 32 spans all banks -> conflict-free MMA fetches).
// ============================================================================
#define XS 40   // smem row stride in halfs

template<int K, bool HALF_IN>
__global__ void k_gemm_tc(const float* __restrict__ Xf, int n) {
    __shared__ __align__(16) __half sX[128 * XS];  // [r][k] chunk, stride 40
    __shared__ __align__(16) __half sW[64 * XS];   // [n][k] chunk, stride 40

    const __half* __restrict__ Wt = (K == 128) ? g_W1t : g_W2t;

    int tid = threadIdx.x;
    int lane = tid & 31;
    int warp = tid >> 5;
    int warp_m = warp & 3;
    int warp_n = warp >> 2;
    int g = lane >> 2;
    int tig = lane & 3;
    int row0 = blockIdx.x * 128;

    float acc[2][4][4];
#pragma unroll
    for (int mt = 0; mt < 2; mt++)
#pragma unroll
        for (int nt = 0; nt < 4; nt++)
#pragma unroll
            for (int c = 0; c < 4; c++) acc[mt][nt][c] = 0.f;

#pragma unroll
    for (int kc = 0; kc < K; kc += 32) {
        // ---- load X chunk [128][32] ----
        if (HALF_IN) {
            // 128 rows x 32 halfs = 512 uint4; 2 per thread
#pragma unroll
            for (int p = 0; p < 2; p++) {
                int l = tid + p * 256;
                int r = l >> 2, q = l & 3;       // q: which 8-half group
                int gr = row0 + r;
                if (gr < n) {
                    *reinterpret_cast<uint4*>(&sX[r * XS + q * 8]) =
                        *reinterpret_cast<const uint4*>(g_B + (size_t)gr * 64 + kc + q * 8);
                }
            }
        } else {
            // 128 rows x 32 floats = 1024 float4; 4 per thread
#pragma unroll
            for (int p = 0; p < 4; p++) {
                int l = tid + p * 256;
                int r = l >> 3, c4 = l & 7;      // c4: which float4 (4 floats)
                int gr = row0 + r;
                if (gr < n) {
                    float4 v = *reinterpret_cast<const float4*>(Xf + (size_t)gr * K + kc + c4 * 4);
                    *reinterpret_cast<__half2*>(&sX[r * XS + c4 * 4])     = __floats2half2_rn(v.x, v.y);
                    *reinterpret_cast<__half2*>(&sX[r * XS + c4 * 4 + 2]) = __floats2half2_rn(v.z, v.w);
                }
            }
        }
        // ---- load W chunk [64][32]: 256 uint4, 1 per thread ----
        {
            int r = tid >> 2, q = tid & 3;
            *reinterpret_cast<uint4*>(&sW[r * XS + q * 8]) =
                *reinterpret_cast<const uint4*>(Wt + (size_t)r * K + kc + q * 8);
        }
        __syncthreads();

#pragma unroll
        for (int k16 = 0; k16 < 32; k16 += 16) {
#pragma unroll
            for (int mt = 0; mt < 2; mt++) {
                int ar = warp_m * 32 + mt * 16;
                unsigned a0 = *reinterpret_cast<unsigned*>(&sX[(ar + g) * XS + k16 + tig * 2]);
                unsigned a1 = *reinterpret_cast<unsigned*>(&sX[(ar + g + 8) * XS + k16 + tig * 2]);
                unsigned a2 = *reinterpret_cast<unsigned*>(&sX[(ar + g) * XS + k16 + tig * 2 + 8]);
                unsigned a3 = *reinterpret_cast<unsigned*>(&sX[(ar + g + 8) * XS + k16 + tig * 2 + 8]);
#pragma unroll
                for (int nt = 0; nt < 4; nt++) {
                    int col = warp_n * 32 + nt * 8 + g;
                    unsigned b0 = *reinterpret_cast<unsigned*>(&sW[col * XS + k16 + tig * 2]);
                    unsigned b1 = *reinterpret_cast<unsigned*>(&sW[col * XS + k16 + tig * 2 + 8]);
                    float* c = acc[mt][nt];
                    asm volatile(
                        "mma.sync.aligned.m16n8k16.row.col.f32.f16.f16.f32 "
                        "{%0,%1,%2,%3},{%4,%5,%6,%7},{%8,%9},{%0,%1,%2,%3};"
                        : "+f"(c[0]), "+f"(c[1]), "+f"(c[2]), "+f"(c[3])
                        : "r"(a0), "r"(a1), "r"(a2), "r"(a3), "r"(b0), "r"(b1));
                }
            }
        }
        __syncthreads();
    }

#pragma unroll
    for (int mt = 0; mt < 2; mt++) {
        int row = row0 + warp_m * 32 + mt * 16 + g;
        float s0 = (row     < n) ? rsqrtf((float)max(g_deg_out[row], 1))     : 0.f;
        float s1 = (row + 8 < n) ? rsqrtf((float)max(g_deg_out[row + 8], 1)) : 0.f;
#pragma unroll
        for (int nt = 0; nt < 4; nt++) {
            int col = warp_n * 32 + nt * 8 + tig * 2;
            float* c = acc[mt][nt];
            if (row < n)
                *reinterpret_cast<__half2*>(g_A + (size_t)row * 64 + col) =
                    __floats2half2_rn(c[0] * s0, c[1] * s0);
            if (row + 8 < n)
                *reinterpret_cast<__half2*>(g_A + (size_t)(row + 8) * 64 + col) =
                    __floats2half2_rn(c[2] * s1, c[3] * s1);
        }
    }
}

// ============================================================================
// CSR aggregate, warp per node. 8 lanes per edge (lane loads uint4 = 8 halfs),
// 8 edges in flight. Segment = [ptr, ptr + deg_in).
// ============================================================================
template<int LAYER>
__global__ void k_agg(const float* __restrict__ bias, float* __restrict__ outp, int n) {
    int gw = (blockIdx.x * blockDim.x + threadIdx.x) >> 5;
    int lane = threadIdx.x & 31;
    if (gw >= n) return;

    int s0 = g_csr_ptr[gw];
    int deg = g_deg_in[gw];
    int s1 = s0 + deg;
    int sub = lane & 7;
    int grp = lane >> 3;

    float acc[8];
#pragma unroll
    for (int j = 0; j < 8; j++) acc[j] = 0.f;

    for (int base = s0; base < s1; base += 8) {
        int e0 = base + grp;
        int e1 = base + 4 + grp;
        uint4 h0 = make_uint4(0u, 0u, 0u, 0u);
        uint4 h1 = make_uint4(0u, 0u, 0u, 0u);
        if (e0 < s1) {
            int s = g_csr_src[e0];
            h0 = *reinterpret_cast<const uint4*>(g_A + (size_t)s * 64 + sub * 8);
        }
        if (e1 < s1) {
            int s = g_csr_src[e1];
            h1 = *reinterpret_cast<const uint4*>(g_A + (size_t)s * 64 + sub * 8);
        }
        const __half2* p0 = reinterpret_cast<const __half2*>(&h0);
        const __half2* p1 = reinterpret_cast<const __half2*>(&h1);
#pragma unroll
        for (int q = 0; q < 4; q++) {
            float2 f0 = __half22float2(p0[q]);
            float2 f1 = __half22float2(p1[q]);
            acc[q * 2]     += f0.x + f1.x;
            acc[q * 2 + 1] += f0.y + f1.y;
        }
    }

#pragma unroll
    for (int j = 0; j < 8; j++) {
        acc[j] += __shfl_xor_sync(0xffffffffu, acc[j], 8);
        acc[j] += __shfl_xor_sync(0xffffffffu, acc[j], 16);
    }

    if (grp == 0) {
        float sc = rsqrtf((float)max(deg, 1));
        const float* bp = bias + sub * 8;
        float o[8];
#pragma unroll
        for (int j = 0; j < 8; j++) {
            o[j] = fmaf(acc[j], sc, bp[j]);
            if (LAYER == 1) o[j] = fmaxf(o[j], 0.f);
        }
        if (LAYER == 1) {
            uint4 pack;
            __half2* hp = reinterpret_cast<__half2*>(&pack);
            hp[0] = __floats2half2_rn(o[0], o[1]);
            hp[1] = __floats2half2_rn(o[2], o[3]);
            hp[2] = __floats2half2_rn(o[4], o[5]);
            hp[3] = __floats2half2_rn(o[6], o[7]);
            *reinterpret_cast<uint4*>(g_B + (size_t)gw * 64 + sub * 8) = pack;
        } else {
            float* op = outp + (size_t)gw * 64 + sub * 8;
            *reinterpret_cast<float4*>(op)     = make_float4(o[0], o[1], o[2], o[3]);
            *reinterpret_cast<float4*>(op + 4) = make_float4(o[4], o[5], o[6], o[7]);
        }
    }
}

extern "C" void kernel_launch(void* const* d_in, const int* in_sizes, int n_in,
                              void* d_out, int out_size) {
    const float* x   = (const float*)d_in[0];
    const int*   src = (const int*)d_in[1];
    const int*   dst = (const int*)d_in[2];
    const float* W1  = (const float*)d_in[3];
    const float* b1  = (const float*)d_in[4];
    const float* W2  = (const float*)d_in[5];
    const float* b2  = (const float*)d_in[6];
    float* out = (float*)d_out;

    const int n = NN;
    const int E = in_sizes[1];

    const int T = 256;
    int grid_e4    = ((E + 3) / 4 + T - 1) / T;   // 4 edges per thread
    int grid_nodes = (n + T - 1) / T;
    int grid_gemm  = (n + 127) / 128;
    int grid_agg   = (n * 32 + T - 1) / T;

    cudaStream_t s1;
    cudaStreamCreateWithFlags(&s1, cudaStreamNonBlocking);
    cudaEvent_t evFork, evJoin;
    cudaEventCreateWithFlags(&evFork, cudaEventDisableTiming);
    cudaEventCreateWithFlags(&evJoin, cudaEventDisableTiming);

    // serial prefix: prep, fused degrees
    k_prep<<<grid_nodes, T>>>(W1, W2, n);
    k_deg<<<grid_e4, T>>>(src, dst, E);
    cudaEventRecord(evFork, 0);
    cudaStreamWaitEvent(s1, evFork, 0);

    // branch A (main): GEMM1 (tensor + DRAM reads of x)
    k_gemm_tc<128, false><<<grid_gemm, T>>>(x, n);

    // branch B (s1): segment assign -> CSR fill (L2 atomics)
    k_assign<<<grid_nodes, T, 0, s1>>>(n);
    k_fill<<<grid_e4, T, 0, s1>>>(src, dst, E);
    cudaEventRecord(evJoin, s1);
    cudaStreamWaitEvent(0, evJoin, 0);

    // layer 1 aggregate, layer 2
    k_agg<1><<<grid_agg, T>>>(b1, nullptr, n);
    k_gemm_tc<64, true><<<grid_gemm, T>>>(nullptr, n);
    k_agg<2><<<grid_agg, T>>>(b2, out, n);

    cudaEventDestroy(evFork);
    cudaEventDestroy(evJoin);
    cudaStreamDestroy(s1);
}